// round 15
// baseline (speedup 1.0000x reference)
#include <cuda_runtime.h>
#include <cuda_fp16.h>
#include <mma.h>

using namespace nvcuda;

#define N_NODES 50000
#define N_EDGES 1600000
#define D 128

#define SCAN_B 256
#define SCAN_NBLK ((N_NODES + SCAN_B - 1) / SCAN_B)   // 196

// Scratch (allocation-free rule: __device__ globals)
__device__ __half g_feath[N_NODES * D];   // norm[s]*feat[s], fp16
__device__ __half g_buf0h[N_NODES * D];   // norm[d]^2 * hop1-sum, fp16
__device__ __half g_Wh[D * D];            // W in fp16
__device__ int    g_cnt[N_NODES];
__device__ unsigned short g_rank[N_EDGES];
__device__ int    g_rowptr[N_NODES + 1];
__device__ int    g_csr_src[N_EDGES];
__device__ float  g_norm[N_NODES];
__device__ int    g_blocksum[SCAN_NBLK];

// ---------------------------------------------------------------------------
// Degree histogram; atomic return value = this edge's rank within its dst.
// ---------------------------------------------------------------------------
__global__ void k_deg_rank(const int* __restrict__ dst) {
    int e = blockIdx.x * blockDim.x + threadIdx.x;
    if (e < N_EDGES) {
        g_rank[e] = (unsigned short)atomicAdd(&g_cnt[dst[e]], 1);
    }
}

// ---------------------------------------------------------------------------
// Scan pass 1: per-block (256-wide) exclusive scan of g_cnt, block totals.
// ---------------------------------------------------------------------------
__global__ void __launch_bounds__(SCAN_B) k_scan1() {
    __shared__ int warp_sums[8];
    int i = blockIdx.x * SCAN_B + threadIdx.x;
    int v = (i < N_NODES) ? g_cnt[i] : 0;

    int lane = threadIdx.x & 31;
    int wid  = threadIdx.x >> 5;
    int s = v;
#pragma unroll
    for (int off = 1; off < 32; off <<= 1) {
        int u = __shfl_up_sync(0xffffffffu, s, off);
        if (lane >= off) s += u;
    }
    if (lane == 31) warp_sums[wid] = s;
    __syncthreads();
    if (wid == 0 && lane < 8) {
        int w = warp_sums[lane];
        int wv = w;
#pragma unroll
        for (int off = 1; off < 8; off <<= 1) {
            int u = __shfl_up_sync(0xffu, wv, off);
            if (lane >= off) wv += u;
        }
        warp_sums[lane] = wv - w;
    }
    __syncthreads();
    int incl = s + warp_sums[wid];
    if (i < N_NODES) g_rowptr[i] = incl - v;
    if (threadIdx.x == SCAN_B - 1) g_blocksum[blockIdx.x] = incl;
}

// ---------------------------------------------------------------------------
// Scan pass 2: block offsets via shared atomics, + norm, close rowptr,
// + W -> fp16.
// ---------------------------------------------------------------------------
__global__ void __launch_bounds__(SCAN_B) k_scan2(const float* __restrict__ W) {
    __shared__ int off;
    int t = threadIdx.x;
    if (t == 0) off = 0;
    __syncthreads();
    for (int b = t; b < blockIdx.x; b += SCAN_B) {
        atomicAdd(&off, g_blocksum[b]);
    }
    __syncthreads();
    int o = off;
    int i = blockIdx.x * SCAN_B + t;
    if (i < N_NODES) {
        g_rowptr[i] += o;
        g_norm[i] = rsqrtf(fmaxf((float)g_cnt[i], 1.0f));
    }
    if (i == 0) g_rowptr[N_NODES] = N_EDGES;
    int wi = blockIdx.x * SCAN_B + t;
    if (wi < D * D) g_Wh[wi] = __float2half(W[wi]);
}

// ---------------------------------------------------------------------------
// CSR fill + feat'=norm*feat fp16 conversion.
// 4 edges per thread (quarter splits) -> 4 independent scatter chains,
// no tail branch. 400k threads x 4 float4 groups covers N_NODES*D exactly.
// ---------------------------------------------------------------------------
#define FILL_Q (N_EDGES / 4)   // 400000
__global__ void k_fill_cvt(const int* __restrict__ src,
                           const int* __restrict__ dst,
                           const float* __restrict__ feat) {
    int i = blockIdx.x * blockDim.x + threadIdx.x;
    if (i >= FILL_Q) return;

#pragma unroll
    for (int h = 0; h < 4; h++) {
        int e = i + h * FILL_Q;
        int d = dst[e];
        g_csr_src[g_rowptr[d] + g_rank[e]] = src[e];
    }

#pragma unroll
    for (int h = 0; h < 4; h++) {
        int e = i + h * FILL_Q;          // float4-group index
        int row = e >> 5;                // 32 groups per row
        float nm = g_norm[row];
        float4 v = ((const float4*)feat)[e];
        __half2 h0 = __floats2half2_rn(nm * v.x, nm * v.y);
        __half2 h1 = __floats2half2_rn(nm * v.z, nm * v.w);
        uint2 u;
        u.x = *(unsigned int*)&h0;
        u.y = *(unsigned int*)&h1;
        ((uint2*)g_feath)[e] = u;
    }
}

// ---------------------------------------------------------------------------
// Shared gather macro: accumulate one fp16 row-slice (uint4) into acc[8].
// ---------------------------------------------------------------------------
#define ACC_U4(u)                                                     \
    do {                                                              \
        __half2* _h = (__half2*)&(u);                                 \
        float2 _f0 = __half22float2(_h[0]);                           \
        float2 _f1 = __half22float2(_h[1]);                           \
        float2 _f2 = __half22float2(_h[2]);                           \
        float2 _f3 = __half22float2(_h[3]);                           \
        acc[0] += _f0.x; acc[1] += _f0.y;                             \
        acc[2] += _f1.x; acc[3] += _f1.y;                             \
        acc[4] += _f2.x; acc[5] += _f2.y;                             \
        acc[6] += _f3.x; acc[7] += _f3.y;                             \
    } while (0)

// ---------------------------------------------------------------------------
// Hop 1: half-warp per node.  buf0h[d] = norm[d]^2 * sum feath[s].
// ---------------------------------------------------------------------------
__global__ void __launch_bounds__(256) k_hop1() {
    int hw   = (blockIdx.x * blockDim.x + threadIdx.x) >> 4;
    int lane = threadIdx.x & 15;
    if (hw >= N_NODES) return;

    const uint4* in4 = (const uint4*)g_feath;
    int beg = g_rowptr[hw];
    int end = g_rowptr[hw + 1];
    float acc[8] = {0.f, 0.f, 0.f, 0.f, 0.f, 0.f, 0.f, 0.f};

    int e = beg;
    for (; e + 4 <= end; e += 4) {
        int s0 = __ldg(&g_csr_src[e + 0]), s1 = __ldg(&g_csr_src[e + 1]);
        int s2 = __ldg(&g_csr_src[e + 2]), s3 = __ldg(&g_csr_src[e + 3]);
        uint4 u0 = __ldg(in4 + s0 * 16 + lane);
        uint4 u1 = __ldg(in4 + s1 * 16 + lane);
        uint4 u2 = __ldg(in4 + s2 * 16 + lane);
        uint4 u3 = __ldg(in4 + s3 * 16 + lane);
        ACC_U4(u0); ACC_U4(u1); ACC_U4(u2); ACC_U4(u3);
    }
    for (; e < end; e++) {
        int s = __ldg(&g_csr_src[e]);
        uint4 u = __ldg(in4 + s * 16 + lane);
        ACC_U4(u);
    }

    float nd = g_norm[hw];
    float scale = nd * nd;
#pragma unroll
    for (int j = 0; j < 8; j++) acc[j] *= scale;

    __half2 h0 = __floats2half2_rn(acc[0], acc[1]);
    __half2 h1 = __floats2half2_rn(acc[2], acc[3]);
    __half2 h2 = __floats2half2_rn(acc[4], acc[5]);
    __half2 h3 = __floats2half2_rn(acc[6], acc[7]);
    uint4 u;
    u.x = *(unsigned int*)&h0;
    u.y = *(unsigned int*)&h1;
    u.z = *(unsigned int*)&h2;
    u.w = *(unsigned int*)&h3;
    ((uint4*)g_buf0h)[hw * 16 + lane] = u;
}

// ---------------------------------------------------------------------------
// FUSED hop2 + GEMM.
// Phase 1: each block computes hop-2 rows for 64 nodes into a smem fp16 tile
//          (16 half-warps x 4 nodes; A[local] = norm[d] * sum buf0h[s]).
// Phase 2: 8 warps run the wmma 64x128 GEMM from smem (bias-folded accums).
// Kills the 12.8MB buf1h write + 12.8MB re-read and one launch.
// ---------------------------------------------------------------------------
#define FBM 64
__global__ void __launch_bounds__(256) k_hop2_gemm(const float* __restrict__ bias,
                                                   float* __restrict__ out) {
    __shared__ __half sA[FBM][D];      // 16 KB
    __shared__ float sbias[16][128];   // 8 KB

    int t = threadIdx.x;
#pragma unroll
    for (int i = 0; i < 8; i++) {
        int idx = t + i * 256;
        sbias[idx >> 7][idx & 127] = bias[idx & 127];
    }

    int hwid = t >> 4;          // half-warp id 0..15
    int lane = t & 15;
    int row0 = blockIdx.x * FBM;

    const uint4* in4 = (const uint4*)g_buf0h;

    // Phase 1: 4 nodes per half-warp (locals hwid, hwid+16, +32, +48)
#pragma unroll
    for (int it = 0; it < 4; it++) {
        int local = hwid + it * 16;
        int node  = row0 + local;
        float acc[8] = {0.f, 0.f, 0.f, 0.f, 0.f, 0.f, 0.f, 0.f};
        if (node < N_NODES) {
            int beg = g_rowptr[node];
            int end = g_rowptr[node + 1];
            int e = beg;
            for (; e + 4 <= end; e += 4) {
                int s0 = __ldg(&g_csr_src[e + 0]), s1 = __ldg(&g_csr_src[e + 1]);
                int s2 = __ldg(&g_csr_src[e + 2]), s3 = __ldg(&g_csr_src[e + 3]);
                uint4 u0 = __ldg(in4 + s0 * 16 + lane);
                uint4 u1 = __ldg(in4 + s1 * 16 + lane);
                uint4 u2 = __ldg(in4 + s2 * 16 + lane);
                uint4 u3 = __ldg(in4 + s3 * 16 + lane);
                ACC_U4(u0); ACC_U4(u1); ACC_U4(u2); ACC_U4(u3);
            }
            for (; e < end; e++) {
                int s = __ldg(&g_csr_src[e]);
                uint4 u = __ldg(in4 + s * 16 + lane);
                ACC_U4(u);
            }
            float nd = g_norm[node];
#pragma unroll
            for (int j = 0; j < 8; j++) acc[j] *= nd;
        }
        __half2 h0 = __floats2half2_rn(acc[0], acc[1]);
        __half2 h1 = __floats2half2_rn(acc[2], acc[3]);
        __half2 h2 = __floats2half2_rn(acc[4], acc[5]);
        __half2 h3 = __floats2half2_rn(acc[6], acc[7]);
        uint4 u;
        u.x = *(unsigned int*)&h0;
        u.y = *(unsigned int*)&h1;
        u.z = *(unsigned int*)&h2;
        u.w = *(unsigned int*)&h3;
        *(uint4*)&sA[local][lane * 8] = u;
    }
    __syncthreads();

    // Phase 2: wmma GEMM from smem A-tile
    int warp = t >> 5;
    int wm = warp >> 1;          // 0..3
    int wn = warp & 1;           // 0..1
    int r0 = wm * 16;
    int col0 = wn * 64;

    wmma::fragment<wmma::accumulator, 16, 16, 16, float> acc[4];
#pragma unroll
    for (int j = 0; j < 4; j++)
        wmma::load_matrix_sync(acc[j], &sbias[0][col0 + j * 16], 128,
                               wmma::mem_row_major);

#pragma unroll
    for (int k0 = 0; k0 < D; k0 += 16) {
        wmma::fragment<wmma::matrix_a, 16, 16, 16, __half, wmma::row_major> a;
        wmma::load_matrix_sync(a, &sA[r0][k0], D);
#pragma unroll
        for (int j = 0; j < 4; j++) {
            wmma::fragment<wmma::matrix_b, 16, 16, 16, __half, wmma::col_major> b;
            wmma::load_matrix_sync(b, g_Wh + (size_t)(col0 + j * 16) * D + k0, D);
            wmma::mma_sync(acc[j], a, b, acc[j]);
        }
    }

    if (row0 + r0 + 16 <= N_NODES) {
#pragma unroll
        for (int j = 0; j < 4; j++)
            wmma::store_matrix_sync(out + (size_t)(row0 + r0) * D + col0 + j * 16,
                                    acc[j], D, wmma::mem_row_major);
    }
}

// ---------------------------------------------------------------------------
// kernel_launch
// ---------------------------------------------------------------------------
extern "C" void kernel_launch(void* const* d_in, const int* in_sizes, int n_in,
                              void* d_out, int out_size) {
    const float* feat = (const float*)d_in[0];
    const int*   src  = (const int*)d_in[1];
    const int*   dst  = (const int*)d_in[2];
    const float* W    = (const float*)d_in[3];
    const float* bias = (const float*)d_in[4];
    float*       out  = (float*)d_out;

    const int gEdge = (N_EDGES + 255) / 256;
    const int gFill = (FILL_Q + 255) / 256;
    const int gHop  = (N_NODES * 16 + 255) / 256;        // half-warp per node
    const int gFuse = (N_NODES + FBM - 1) / FBM;         // 782

    void* p = nullptr;
    cudaGetSymbolAddress(&p, g_cnt);
    cudaMemsetAsync(p, 0, N_NODES * sizeof(int), 0);

    k_deg_rank  <<<gEdge, 256>>>(dst);
    k_scan1     <<<SCAN_NBLK, SCAN_B>>>();
    k_scan2     <<<SCAN_NBLK, SCAN_B>>>(W);        // offsets + norm + W->fp16
    k_fill_cvt  <<<gFill, 256>>>(src, dst, feat);  // CSR + feat'*norm fp16
    k_hop1      <<<gHop, 256>>>();                 // g_feath -> g_buf0h
    k_hop2_gemm <<<gFuse, 256>>>(bias, out);       // g_buf0h -> out (fused)
}

// round 16
// speedup vs baseline: 1.0183x; 1.0183x over previous
#include <cuda_runtime.h>
#include <cuda_fp16.h>
#include <mma.h>

using namespace nvcuda;

#define N_NODES 50000
#define N_EDGES 1600000
#define D 128

#define SCAN_B 256
#define SCAN_NBLK ((N_NODES + SCAN_B - 1) / SCAN_B)   // 196

#define N_PAD 50048   // N_NODES padded to multiple of 64 for wmma A-loads

// Scratch (allocation-free rule: __device__ globals)
__device__ __half g_feath[N_NODES * D];   // norm[s]*feat[s], fp16
__device__ __half g_buf0h[N_NODES * D];   // norm[d]^2 * hop1-sum, fp16
__device__ __half g_buf1h[N_PAD * D];     // final hop2 output, fp16 (GEMM A)
__device__ __half g_Wh[D * D];            // W in fp16
__device__ int    g_cnt[N_NODES];
__device__ unsigned short g_rank[N_EDGES];
__device__ int    g_rowptr[N_NODES + 1];
__device__ int    g_csr_src[N_EDGES];
__device__ float  g_norm[N_NODES];
__device__ int    g_aggval[SCAN_NBLK];    // per-block scan totals
__device__ int    g_prefoff[SCAN_NBLK];   // per-block exclusive offsets
__device__ int    g_sync[2];              // [0]=arrival counter, [1]=done flag

// ---------------------------------------------------------------------------
// Degree histogram; atomic return value = this edge's rank within its dst.
// ---------------------------------------------------------------------------
__global__ void k_deg_rank(const int* __restrict__ dst) {
    int e = blockIdx.x * blockDim.x + threadIdx.x;
    if (e < N_EDGES) {
        g_rank[e] = (unsigned short)atomicAdd(&g_cnt[dst[e]], 1);
    }
}

// ---------------------------------------------------------------------------
// SINGLE-PASS scan (fused scan1+scan2): local exclusive scan, last-arriving
// block scans the 196 partials, everyone applies offset. All 196 blocks are
// co-resident (<< 1184 capacity) so the spin cannot deadlock.
// Also: norm = rsqrt(clip(deg,1)), close rowptr, W -> fp16.
// ---------------------------------------------------------------------------
__global__ void __launch_bounds__(SCAN_B) k_scan(const float* __restrict__ W) {
    __shared__ int warp_sums[8];
    __shared__ int s_off;
    int b = blockIdx.x;
    int i = b * SCAN_B + threadIdx.x;
    int v = (i < N_NODES) ? g_cnt[i] : 0;

    // local exclusive scan (shuffle)
    int lane = threadIdx.x & 31;
    int wid  = threadIdx.x >> 5;
    int s = v;
#pragma unroll
    for (int off = 1; off < 32; off <<= 1) {
        int u = __shfl_up_sync(0xffffffffu, s, off);
        if (lane >= off) s += u;
    }
    if (lane == 31) warp_sums[wid] = s;
    __syncthreads();
    if (wid == 0 && lane < 8) {
        int w = warp_sums[lane];
        int wv = w;
#pragma unroll
        for (int off = 1; off < 8; off <<= 1) {
            int u = __shfl_up_sync(0xffu, wv, off);
            if (lane >= off) wv += u;
        }
        warp_sums[lane] = wv - w;   // exclusive warp offsets
    }
    __syncthreads();
    int incl = s + warp_sums[wid];
    int local_excl = incl - v;

    // publish block total
    if (threadIdx.x == SCAN_B - 1) g_aggval[b] = incl;
    __threadfence();
    __syncthreads();

    // last-block computes all 196 offsets; others spin on done flag
    if (threadIdx.x == 0) {
        int old = atomicAdd(&g_sync[0], 1);
        if (old == SCAN_NBLK - 1) {
            int acc = 0;
            for (int j = 0; j < SCAN_NBLK; j++) {
                int a = g_aggval[j];
                g_prefoff[j] = acc;
                acc += a;
            }
            __threadfence();
            atomicExch(&g_sync[1], 1);
        }
        while (atomicAdd(&g_sync[1], 0) == 0) {}
        s_off = g_prefoff[b];
    }
    __syncthreads();
    int o = s_off;

    if (i < N_NODES) {
        g_rowptr[i] = local_excl + o;
        g_norm[i] = rsqrtf(fmaxf((float)v, 1.0f));
    }
    if (i == 0) g_rowptr[N_NODES] = N_EDGES;
    if (i < D * D) g_Wh[i] = __float2half(W[i]);
}

// ---------------------------------------------------------------------------
// CSR fill + feat'=norm*feat fp16 conversion + GEMM pad-zero.
// (R14-proven shape: 2 edges/thread split halves, 19.3us.)
// ---------------------------------------------------------------------------
#define FILL_T (N_EDGES / 2)   // 800000
__global__ void k_fill_cvt(const int* __restrict__ src,
                           const int* __restrict__ dst,
                           const float* __restrict__ feat) {
    int i = blockIdx.x * blockDim.x + threadIdx.x;
    if (i >= FILL_T) return;
    int e0 = i;
    int e1 = i + FILL_T;

    int d0 = dst[e0], d1 = dst[e1];
    int s0 = src[e0], s1 = src[e1];
    int r0 = g_rank[e0], r1 = g_rank[e1];
    int p0 = g_rowptr[d0], p1 = g_rowptr[d1];
    g_csr_src[p0 + r0] = s0;
    g_csr_src[p1 + r1] = s1;

#pragma unroll
    for (int h = 0; h < 2; h++) {
        int e = i + h * FILL_T;          // float4-group index
        int row = e >> 5;                // 32 groups per row
        float nm = g_norm[row];
        float4 v = ((const float4*)feat)[e];
        __half2 h0 = __floats2half2_rn(nm * v.x, nm * v.y);
        __half2 h1 = __floats2half2_rn(nm * v.z, nm * v.w);
        uint2 u;
        u.x = *(unsigned int*)&h0;
        u.y = *(unsigned int*)&h1;
        ((uint2*)g_feath)[e] = u;
    }
    // pad rows N_NODES..N_PAD-1 of g_buf1h: 48*128 halves = 1536 uint2
    if (i < (N_PAD - N_NODES) * D / 4) {
        ((uint2*)(g_buf1h + N_NODES * D))[i] = make_uint2(0u, 0u);
    }
}

// ---------------------------------------------------------------------------
// Pull-mode hop, half-warp per dst node, norm-free inner loop:
//   HOP=1: buf0h[d] = norm[d]^2 * sum_{s in N(d)} feath[s]
//   HOP=2: buf1h[d] = norm[d]   * sum_{s in N(d)} buf0h[s]
// ---------------------------------------------------------------------------
template <int HOP>
__global__ void __launch_bounds__(256) k_hop() {
    int hw   = (blockIdx.x * blockDim.x + threadIdx.x) >> 4;   // node id
    int lane = threadIdx.x & 15;
    if (hw >= N_NODES) return;

    const uint4* in4 = (const uint4*)((HOP == 1) ? g_feath : g_buf0h);

    int beg = g_rowptr[hw];
    int end = g_rowptr[hw + 1];
    float acc[8] = {0.f, 0.f, 0.f, 0.f, 0.f, 0.f, 0.f, 0.f};

#define ACC_U4(u)                                                     \
    do {                                                              \
        __half2* _h = (__half2*)&(u);                                 \
        float2 _f0 = __half22float2(_h[0]);                           \
        float2 _f1 = __half22float2(_h[1]);                           \
        float2 _f2 = __half22float2(_h[2]);                           \
        float2 _f3 = __half22float2(_h[3]);                           \
        acc[0] += _f0.x; acc[1] += _f0.y;                             \
        acc[2] += _f1.x; acc[3] += _f1.y;                             \
        acc[4] += _f2.x; acc[5] += _f2.y;                             \
        acc[6] += _f3.x; acc[7] += _f3.y;                             \
    } while (0)

    int e = beg;
    for (; e + 4 <= end; e += 4) {
        int s0 = __ldg(&g_csr_src[e + 0]), s1 = __ldg(&g_csr_src[e + 1]);
        int s2 = __ldg(&g_csr_src[e + 2]), s3 = __ldg(&g_csr_src[e + 3]);
        uint4 u0 = __ldg(in4 + s0 * 16 + lane);
        uint4 u1 = __ldg(in4 + s1 * 16 + lane);
        uint4 u2 = __ldg(in4 + s2 * 16 + lane);
        uint4 u3 = __ldg(in4 + s3 * 16 + lane);
        ACC_U4(u0);
        ACC_U4(u1);
        ACC_U4(u2);
        ACC_U4(u3);
    }
    for (; e < end; e++) {
        int s = __ldg(&g_csr_src[e]);
        uint4 u = __ldg(in4 + s * 16 + lane);
        ACC_U4(u);
    }
#undef ACC_U4

    float nd = g_norm[hw];
    float scale = (HOP == 1) ? nd * nd : nd;
#pragma unroll
    for (int j = 0; j < 8; j++) acc[j] *= scale;

    __half2 h0 = __floats2half2_rn(acc[0], acc[1]);
    __half2 h1 = __floats2half2_rn(acc[2], acc[3]);
    __half2 h2 = __floats2half2_rn(acc[4], acc[5]);
    __half2 h3 = __floats2half2_rn(acc[6], acc[7]);
    uint4 u;
    u.x = *(unsigned int*)&h0;
    u.y = *(unsigned int*)&h1;
    u.z = *(unsigned int*)&h2;
    u.w = *(unsigned int*)&h3;
    __half* outp = (HOP == 1) ? g_buf0h : g_buf1h;
    ((uint4*)outp)[hw * 16 + lane] = u;
}

// ---------------------------------------------------------------------------
// Tensor-core GEMM: out[n][o] = sum_k A[n][k] * W[o][k] + b[o]
// (R11-proven, ~10us.)
// ---------------------------------------------------------------------------
#define GBM 64
__global__ void __launch_bounds__(256) k_gemm(const float* __restrict__ bias,
                                              float* __restrict__ out) {
    __shared__ float sbias[16][128];

    int t = threadIdx.x;
#pragma unroll
    for (int i = 0; i < 8; i++) {
        int idx = t + i * 256;
        sbias[idx >> 7][idx & 127] = bias[idx & 127];
    }
    __syncthreads();

    int warp = t >> 5;
    int wm = warp >> 1;
    int wn = warp & 1;
    int row0 = blockIdx.x * GBM + wm * 16;
    int col0 = wn * 64;

    wmma::fragment<wmma::accumulator, 16, 16, 16, float> acc[4];
#pragma unroll
    for (int j = 0; j < 4; j++)
        wmma::load_matrix_sync(acc[j], &sbias[0][col0 + j * 16], 128,
                               wmma::mem_row_major);

#pragma unroll
    for (int k0 = 0; k0 < D; k0 += 16) {
        wmma::fragment<wmma::matrix_a, 16, 16, 16, __half, wmma::row_major> a;
        wmma::load_matrix_sync(a, g_buf1h + (size_t)row0 * D + k0, D);
#pragma unroll
        for (int j = 0; j < 4; j++) {
            wmma::fragment<wmma::matrix_b, 16, 16, 16, __half, wmma::col_major> b;
            wmma::load_matrix_sync(b, g_Wh + (size_t)(col0 + j * 16) * D + k0, D);
            wmma::mma_sync(acc[j], a, b, acc[j]);
        }
    }

    if (row0 + 16 <= N_NODES) {
#pragma unroll
        for (int j = 0; j < 4; j++)
            wmma::store_matrix_sync(out + (size_t)row0 * D + col0 + j * 16,
                                    acc[j], D, wmma::mem_row_major);
    }
}

// ---------------------------------------------------------------------------
// kernel_launch
// ---------------------------------------------------------------------------
extern "C" void kernel_launch(void* const* d_in, const int* in_sizes, int n_in,
                              void* d_out, int out_size) {
    const float* feat = (const float*)d_in[0];
    const int*   src  = (const int*)d_in[1];
    const int*   dst  = (const int*)d_in[2];
    const float* W    = (const float*)d_in[3];
    const float* bias = (const float*)d_in[4];
    float*       out  = (float*)d_out;

    const int gEdge = (N_EDGES + 255) / 256;
    const int gFill = (FILL_T + 255) / 256;
    const int gHop  = (N_NODES * 16 + 255) / 256;   // half-warp per node
    const int gGemm = (N_PAD + GBM - 1) / GBM;      // 782

    void* p = nullptr;
    cudaGetSymbolAddress(&p, g_cnt);
    cudaMemsetAsync(p, 0, N_NODES * sizeof(int), 0);
    cudaGetSymbolAddress(&p, g_sync);
    cudaMemsetAsync(p, 0, 2 * sizeof(int), 0);

    k_deg_rank<<<gEdge, 256>>>(dst);
    k_scan    <<<SCAN_NBLK, SCAN_B>>>(W);        // single-pass scan + norm + W
    k_fill_cvt<<<gFill, 256>>>(src, dst, feat);  // CSR + feat'*norm fp16 + pad
    k_hop<1>  <<<gHop, 256>>>();                 // g_feath -> g_buf0h
    k_hop<2>  <<<gHop, 256>>>();                 // g_buf0h -> g_buf1h
    k_gemm    <<<gGemm, 256>>>(bias, out);
}

// round 17
// speedup vs baseline: 1.0831x; 1.0636x over previous
#include <cuda_runtime.h>
#include <cuda_fp16.h>
#include <mma.h>

using namespace nvcuda;

#define N_NODES 50000
#define N_EDGES 1600000
#define D 128

#define SCAN_B 256
#define SCAN_NBLK ((N_NODES + SCAN_B - 1) / SCAN_B)   // 196

#define N_PAD 50048   // N_NODES padded to multiple of 64 for wmma A-loads

// Scratch (allocation-free rule: __device__ globals)
__device__ __half g_feath[N_NODES * D];   // norm[s]*feat[s], fp16
__device__ __half g_buf0h[N_NODES * D];   // norm[d]^2 * hop1-sum, fp16
__device__ __half g_buf1h[N_PAD * D];     // final hop2 output, fp16 (GEMM A)
__device__ __half g_Wh[D * D];            // W in fp16
__device__ int    g_cnt[N_NODES];
__device__ unsigned short g_rank[N_EDGES];
__device__ int    g_rowptr[N_NODES + 1];
__device__ int    g_csr_src[N_EDGES];
__device__ float  g_norm[N_NODES];
__device__ int    g_blocksum[SCAN_NBLK];

// ---------------------------------------------------------------------------
// Degree histogram; atomic return value = this edge's rank within its dst.
// ---------------------------------------------------------------------------
__global__ void k_deg_rank(const int* __restrict__ dst) {
    int e = blockIdx.x * blockDim.x + threadIdx.x;
    if (e < N_EDGES) {
        g_rank[e] = (unsigned short)atomicAdd(&g_cnt[dst[e]], 1);
    }
}

// ---------------------------------------------------------------------------
// Scan pass 1: per-block (256-wide) exclusive scan of g_cnt, block totals.
// (R14-proven.)
// ---------------------------------------------------------------------------
__global__ void __launch_bounds__(SCAN_B) k_scan1() {
    __shared__ int warp_sums[8];
    int i = blockIdx.x * SCAN_B + threadIdx.x;
    int v = (i < N_NODES) ? g_cnt[i] : 0;

    int lane = threadIdx.x & 31;
    int wid  = threadIdx.x >> 5;
    int s = v;
#pragma unroll
    for (int off = 1; off < 32; off <<= 1) {
        int u = __shfl_up_sync(0xffffffffu, s, off);
        if (lane >= off) s += u;
    }
    if (lane == 31) warp_sums[wid] = s;
    __syncthreads();
    if (wid == 0 && lane < 8) {
        int w = warp_sums[lane];
        int wv = w;
#pragma unroll
        for (int off = 1; off < 8; off <<= 1) {
            int u = __shfl_up_sync(0xffu, wv, off);
            if (lane >= off) wv += u;
        }
        warp_sums[lane] = wv - w;
    }
    __syncthreads();
    int incl = s + warp_sums[wid];
    if (i < N_NODES) g_rowptr[i] = incl - v;
    if (threadIdx.x == SCAN_B - 1) g_blocksum[blockIdx.x] = incl;
}

// ---------------------------------------------------------------------------
// Scan pass 2: block offsets via shared atomics, + norm, close rowptr,
// + W -> fp16. (R14-proven.)
// ---------------------------------------------------------------------------
__global__ void __launch_bounds__(SCAN_B) k_scan2(const float* __restrict__ W) {
    __shared__ int off;
    int t = threadIdx.x;
    if (t == 0) off = 0;
    __syncthreads();
    for (int b = t; b < blockIdx.x; b += SCAN_B) {
        atomicAdd(&off, g_blocksum[b]);
    }
    __syncthreads();
    int o = off;
    int i = blockIdx.x * SCAN_B + t;
    if (i < N_NODES) {
        g_rowptr[i] += o;
        g_norm[i] = rsqrtf(fmaxf((float)g_cnt[i], 1.0f));
    }
    if (i == 0) g_rowptr[N_NODES] = N_EDGES;
    int wi = blockIdx.x * SCAN_B + t;
    if (wi < D * D) g_Wh[wi] = __float2half(W[wi]);
}

// ---------------------------------------------------------------------------
// CSR fill + feat'=norm*feat fp16 conversion + GEMM pad-zero.
// (R14-proven shape: 2 edges/thread split halves.)
// ---------------------------------------------------------------------------
#define FILL_T (N_EDGES / 2)   // 800000
__global__ void k_fill_cvt(const int* __restrict__ src,
                           const int* __restrict__ dst,
                           const float* __restrict__ feat) {
    int i = blockIdx.x * blockDim.x + threadIdx.x;
    if (i >= FILL_T) return;
    int e0 = i;
    int e1 = i + FILL_T;

    int d0 = dst[e0], d1 = dst[e1];
    int s0 = src[e0], s1 = src[e1];
    int r0 = g_rank[e0], r1 = g_rank[e1];
    int p0 = g_rowptr[d0], p1 = g_rowptr[d1];
    g_csr_src[p0 + r0] = s0;
    g_csr_src[p1 + r1] = s1;

#pragma unroll
    for (int h = 0; h < 2; h++) {
        int e = i + h * FILL_T;          // float4-group index
        int row = e >> 5;                // 32 groups per row
        float nm = g_norm[row];
        float4 v = ((const float4*)feat)[e];
        __half2 h0 = __floats2half2_rn(nm * v.x, nm * v.y);
        __half2 h1 = __floats2half2_rn(nm * v.z, nm * v.w);
        uint2 u;
        u.x = *(unsigned int*)&h0;
        u.y = *(unsigned int*)&h1;
        ((uint2*)g_feath)[e] = u;
    }
    // pad rows N_NODES..N_PAD-1 of g_buf1h: 48*128 halves = 1536 uint2
    if (i < (N_PAD - N_NODES) * D / 4) {
        ((uint2*)(g_buf1h + N_NODES * D))[i] = make_uint2(0u, 0u);
    }
}

// ---------------------------------------------------------------------------
// Pull-mode hop, half-warp per dst node, norm-free inner loop, accumulation
// in PACKED f32x2 (add.rn.f32x2 — one instr = two fp32 adds; sm_103a-only,
// PTX-exposed, bit-identical numerics to scalar fp32 adds).
//   HOP=1: buf0h[d] = norm[d]^2 * sum_{s in N(d)} feath[s]
//   HOP=2: buf1h[d] = norm[d]   * sum_{s in N(d)} buf0h[s]
// ---------------------------------------------------------------------------
template <int HOP>
__global__ void __launch_bounds__(256) k_hop() {
    int hw   = (blockIdx.x * blockDim.x + threadIdx.x) >> 4;   // node id
    int lane = threadIdx.x & 15;
    if (hw >= N_NODES) return;

    const uint4* in4 = (const uint4*)((HOP == 1) ? g_feath : g_buf0h);

    int beg = g_rowptr[hw];
    int end = g_rowptr[hw + 1];

    unsigned long long accp[4] = {0ull, 0ull, 0ull, 0ull};  // 4x packed f32x2

    // Convert one half2 to a packed f32x2 and add into accp[k].
#define ACC_H2(k, h2v)                                                     \
    do {                                                                   \
        float2 _f = __half22float2(h2v);                                   \
        unsigned long long _p;                                             \
        asm("mov.b64 %0, {%1, %2};" : "=l"(_p) : "f"(_f.x), "f"(_f.y));    \
        asm("add.rn.f32x2 %0, %0, %1;" : "+l"(accp[k]) : "l"(_p));         \
    } while (0)

#define ACC_U4(u)                                                          \
    do {                                                                   \
        __half2* _h = (__half2*)&(u);                                      \
        ACC_H2(0, _h[0]);                                                  \
        ACC_H2(1, _h[1]);                                                  \
        ACC_H2(2, _h[2]);                                                  \
        ACC_H2(3, _h[3]);                                                  \
    } while (0)

    int e = beg;
    for (; e + 4 <= end; e += 4) {
        int s0 = __ldg(&g_csr_src[e + 0]), s1 = __ldg(&g_csr_src[e + 1]);
        int s2 = __ldg(&g_csr_src[e + 2]), s3 = __ldg(&g_csr_src[e + 3]);
        uint4 u0 = __ldg(in4 + s0 * 16 + lane);
        uint4 u1 = __ldg(in4 + s1 * 16 + lane);
        uint4 u2 = __ldg(in4 + s2 * 16 + lane);
        uint4 u3 = __ldg(in4 + s3 * 16 + lane);
        ACC_U4(u0);
        ACC_U4(u1);
        ACC_U4(u2);
        ACC_U4(u3);
    }
    for (; e < end; e++) {
        int s = __ldg(&g_csr_src[e]);
        uint4 u = __ldg(in4 + s * 16 + lane);
        ACC_U4(u);
    }
#undef ACC_U4
#undef ACC_H2

    float nd = g_norm[hw];
    float scale = (HOP == 1) ? nd * nd : nd;
    unsigned long long sp;
    asm("mov.b64 %0, {%1, %1};" : "=l"(sp) : "f"(scale));
#pragma unroll
    for (int k = 0; k < 4; k++)
        asm("mul.rn.f32x2 %0, %0, %1;" : "+l"(accp[k]) : "l"(sp));

    // unpack + convert to fp16
    uint4 u;
    {
        float a0, a1, a2, a3, a4, a5, a6, a7;
        asm("mov.b64 {%0, %1}, %2;" : "=f"(a0), "=f"(a1) : "l"(accp[0]));
        asm("mov.b64 {%0, %1}, %2;" : "=f"(a2), "=f"(a3) : "l"(accp[1]));
        asm("mov.b64 {%0, %1}, %2;" : "=f"(a4), "=f"(a5) : "l"(accp[2]));
        asm("mov.b64 {%0, %1}, %2;" : "=f"(a6), "=f"(a7) : "l"(accp[3]));
        __half2 h0 = __floats2half2_rn(a0, a1);
        __half2 h1 = __floats2half2_rn(a2, a3);
        __half2 h2 = __floats2half2_rn(a4, a5);
        __half2 h3 = __floats2half2_rn(a6, a7);
        u.x = *(unsigned int*)&h0;
        u.y = *(unsigned int*)&h1;
        u.z = *(unsigned int*)&h2;
        u.w = *(unsigned int*)&h3;
    }
    __half* outp = (HOP == 1) ? g_buf0h : g_buf1h;
    ((uint4*)outp)[hw * 16 + lane] = u;
}

// ---------------------------------------------------------------------------
// Tensor-core GEMM: out[n][o] = sum_k A[n][k] * W[o][k] + b[o]
// (R11-proven, ~10us.)
// ---------------------------------------------------------------------------
#define GBM 64
__global__ void __launch_bounds__(256) k_gemm(const float* __restrict__ bias,
                                              float* __restrict__ out) {
    __shared__ float sbias[16][128];

    int t = threadIdx.x;
#pragma unroll
    for (int i = 0; i < 8; i++) {
        int idx = t + i * 256;
        sbias[idx >> 7][idx & 127] = bias[idx & 127];
    }
    __syncthreads();

    int warp = t >> 5;
    int wm = warp >> 1;
    int wn = warp & 1;
    int row0 = blockIdx.x * GBM + wm * 16;
    int col0 = wn * 64;

    wmma::fragment<wmma::accumulator, 16, 16, 16, float> acc[4];
#pragma unroll
    for (int j = 0; j < 4; j++)
        wmma::load_matrix_sync(acc[j], &sbias[0][col0 + j * 16], 128,
                               wmma::mem_row_major);

#pragma unroll
    for (int k0 = 0; k0 < D; k0 += 16) {
        wmma::fragment<wmma::matrix_a, 16, 16, 16, __half, wmma::row_major> a;
        wmma::load_matrix_sync(a, g_buf1h + (size_t)row0 * D + k0, D);
#pragma unroll
        for (int j = 0; j < 4; j++) {
            wmma::fragment<wmma::matrix_b, 16, 16, 16, __half, wmma::col_major> b;
            wmma::load_matrix_sync(b, g_Wh + (size_t)(col0 + j * 16) * D + k0, D);
            wmma::mma_sync(acc[j], a, b, acc[j]);
        }
    }

    if (row0 + 16 <= N_NODES) {
#pragma unroll
        for (int j = 0; j < 4; j++)
            wmma::store_matrix_sync(out + (size_t)row0 * D + col0 + j * 16,
                                    acc[j], D, wmma::mem_row_major);
    }
}

// ---------------------------------------------------------------------------
// kernel_launch
// ---------------------------------------------------------------------------
extern "C" void kernel_launch(void* const* d_in, const int* in_sizes, int n_in,
                              void* d_out, int out_size) {
    const float* feat = (const float*)d_in[0];
    const int*   src  = (const int*)d_in[1];
    const int*   dst  = (const int*)d_in[2];
    const float* W    = (const float*)d_in[3];
    const float* bias = (const float*)d_in[4];
    float*       out  = (float*)d_out;

    const int gEdge = (N_EDGES + 255) / 256;
    const int gFill = (FILL_T + 255) / 256;
    const int gHop  = (N_NODES * 16 + 255) / 256;   // half-warp per node
    const int gGemm = (N_PAD + GBM - 1) / GBM;      // 782

    void* p = nullptr;
    cudaGetSymbolAddress(&p, g_cnt);
    cudaMemsetAsync(p, 0, N_NODES * sizeof(int), 0);

    k_deg_rank<<<gEdge, 256>>>(dst);
    k_scan1   <<<SCAN_NBLK, SCAN_B>>>();
    k_scan2   <<<SCAN_NBLK, SCAN_B>>>(W);        // offsets + norm + W->fp16
    k_fill_cvt<<<gFill, 256>>>(src, dst, feat);  // CSR + feat'*norm fp16 + pad
    k_hop<1>  <<<gHop, 256>>>();                 // g_feath -> g_buf0h
    k_hop<2>  <<<gHop, 256>>>();                 // g_buf0h -> g_buf1h
    k_gemm    <<<gGemm, 256>>>(bias, out);
}